// round 3
// baseline (speedup 1.0000x reference)
#include <cuda_runtime.h>
#include <cuda_bf16.h>
#include <math.h>

#define BQ 2
#define S_LEN 2048
#define HK 16
#define HV 32
#define DK 128
#define DV 128
#define QKV 8192
#define NROWS (BQ * S_LEN)

typedef unsigned long long ull;

// ---------------- scratch (device globals; no runtime allocation) ----------------
__device__ float g_qn[(size_t)NROWS * HK * DK];    // l2norm(q) * scale
__device__ float g_kn[(size_t)NROWS * HK * DK];    // l2norm(k)
__device__ float g_v [(size_t)NROWS * HV * DV];
__device__ float g_gate[(size_t)NROWS * HV * 4];   // float4 per (row,h): eg, beta, qk, 0

// ---------------- packed f32x2 helpers ----------------
__device__ __forceinline__ ull pack2(float lo, float hi) {
    ull r;
    asm("mov.b64 %0, {%1,%2};" : "=l"(r) : "f"(lo), "f"(hi));
    return r;
}
__device__ __forceinline__ float2 unpack2(ull v) {
    float2 r;
    asm("mov.b64 {%0,%1}, %2;" : "=f"(r.x), "=f"(r.y) : "l"(v));
    return r;
}
#define FMA2(d, a, b, c) asm("fma.rn.f32x2 %0, %1, %2, %3;" : "=l"(d) : "l"(a), "l"(b), "l"(c))
#define MUL2(d, a, b)    asm("mul.rn.f32x2 %0, %1, %2;"     : "=l"(d) : "l"(a), "l"(b))

union F4U { float4 f; ull u[2]; };

// ---------------- kernel 1: conv + silu + l2norm + qk + gating ----------------
__global__ __launch_bounds__(256) void prep_kernel(
    const float* __restrict__ x,      // [NROWS, QKV]
    const float* __restrict__ bvec,   // [NROWS, HV]
    const float* __restrict__ avec,   // [NROWS, HV]
    const float* __restrict__ w,      // [QKV, 4]
    const float* __restrict__ dt_bias,// [HV]
    const float* __restrict__ alog)   // [HV]
{
    const int row = blockIdx.x;
    const int s   = row & (S_LEN - 1);
    const int tid = threadIdx.x;

    __shared__ float ysm[QKV];            // 32 KB
    __shared__ float qk_s[HK];

    const float4* w4 = (const float4*)w;  // taps contiguous per channel

    // --- phase 1: causal depthwise conv (width 4) + SiLU ---
    for (int base = tid * 4; base < QKV; base += 256 * 4) {
        float4 wv0 = __ldg(w4 + base + 0);
        float4 wv1 = __ldg(w4 + base + 1);
        float4 wv2 = __ldg(w4 + base + 2);
        float4 wv3 = __ldg(w4 + base + 3);
        const float* t0 = (const float*)&wv0;
        const float* t1 = (const float*)&wv1;
        const float* t2 = (const float*)&wv2;
        const float* t3 = (const float*)&wv3;
        float4 acc = make_float4(0.f, 0.f, 0.f, 0.f);
#pragma unroll
        for (int j = 0; j < 4; j++) {
            if (s - 3 + j >= 0) {
                const float4 xv = *reinterpret_cast<const float4*>(
                    x + (size_t)(row - 3 + j) * QKV + base);
                acc.x = fmaf(xv.x, t0[j], acc.x);
                acc.y = fmaf(xv.y, t1[j], acc.y);
                acc.z = fmaf(xv.z, t2[j], acc.z);
                acc.w = fmaf(xv.w, t3[j], acc.w);
            }
        }
        acc.x = acc.x / (1.f + __expf(-acc.x));
        acc.y = acc.y / (1.f + __expf(-acc.y));
        acc.z = acc.z / (1.f + __expf(-acc.z));
        acc.w = acc.w / (1.f + __expf(-acc.w));
        *reinterpret_cast<float4*>(ysm + base) = acc;
    }
    __syncthreads();

    const int wi   = tid >> 5;
    const int lane = tid & 31;
    const float qscale = 0.08838834764831845f; // 128^-0.5

    // --- phase 2: l2 norms for 32 groups (16 q heads + 16 k heads) ---
    // writes normalized values back to ysm (in place) and to gmem scratch
    for (int gr = wi; gr < 32; gr += 8) {
        const float4 v4 = reinterpret_cast<const float4*>(ysm + gr * 128)[lane];
        float ss = v4.x * v4.x + v4.y * v4.y + v4.z * v4.z + v4.w * v4.w;
#pragma unroll
        for (int o = 16; o > 0; o >>= 1) ss += __shfl_xor_sync(0xffffffffu, ss, o);
        const bool isq = gr < 16;
        const float mul = rsqrtf(ss + 1e-6f) * (isq ? qscale : 1.f);
        float4 ov = make_float4(v4.x * mul, v4.y * mul, v4.z * mul, v4.w * mul);
        reinterpret_cast<float4*>(ysm + gr * 128)[lane] = ov;
        if (isq)
            reinterpret_cast<float4*>(g_qn + ((size_t)row * HK + gr) * DK)[lane] = ov;
        else
            reinterpret_cast<float4*>(g_kn + ((size_t)row * HK + (gr - 16)) * DK)[lane] = ov;
    }

    // --- v copy (reads untouched region of ysm) ---
    for (int i = tid * 4; i < HV * DV; i += 256 * 4)
        *reinterpret_cast<float4*>(g_v + (size_t)row * (HV * DV) + i) =
            *reinterpret_cast<const float4*>(ysm + 2 * HK * DK + i);
    __syncthreads();

    // --- phase 3: qk[hk] = qn . kn (normalized values, qscale included in qn) ---
    for (int hk2 = wi; hk2 < HK; hk2 += 8) {
        const float4 qv = reinterpret_cast<const float4*>(ysm + hk2 * 128)[lane];
        const float4 kv = reinterpret_cast<const float4*>(ysm + (16 + hk2) * 128)[lane];
        float d = qv.x * kv.x + qv.y * kv.y + qv.z * kv.z + qv.w * kv.w;
#pragma unroll
        for (int o = 16; o > 0; o >>= 1) d += __shfl_xor_sync(0xffffffffu, d, o);
        if (lane == 0) qk_s[hk2] = d;
    }
    __syncthreads();

    // --- phase 4: gating table (eg, beta, qk) ---
    if (tid < HV) {
        const int h = tid;
        float aa = avec[(size_t)row * HV + h] + dt_bias[h];
        float sp = (aa > 20.f) ? aa : log1pf(expf(aa));
        float g  = -expf(alog[h]) * sp;
        float eg = expf(g);
        float bb = bvec[(size_t)row * HV + h];
        float beta = 1.f / (1.f + expf(-bb));
        float4 gv = make_float4(eg, beta, qk_s[h >> 1], 0.f);
        *reinterpret_cast<float4*>(g_gate + ((size_t)row * HV + h) * 4) = gv;
    }
}

// ---------------- kernel 2: gated delta-rule recurrence ----------------
// grid: 128 blocks = (b, h, vh). 256 threads = 32 col-pairs x 8 k-slices.
// Thread (c2, p): owns 16 k-dims [p*16, p*16+16) of 2 v-columns {vh*64+2c2, +1}.
// State dim-packed f32x2 per column. No smem, no barriers: k/q/v/gates read
// straight from gmem (L1 absorbs the 8-warp redundancy), register double-buffered.
// Output uses o = q.S_decayed + (q.k) * u, so only ONE shfl-reduction phase per token.

#define FETCH(S, T) do {                                                     \
    const int _t = (T);                                                      \
    const float* _kp = kbase + (size_t)_t * (HK * DK);                       \
    const float* _qp = qbase + (size_t)_t * (HK * DK);                       \
    kb##S[0].f = __ldg((const float4*)(_kp + 0));                            \
    kb##S[1].f = __ldg((const float4*)(_kp + 4));                            \
    kb##S[2].f = __ldg((const float4*)(_kp + 8));                            \
    kb##S[3].f = __ldg((const float4*)(_kp + 12));                           \
    qb##S[0].f = __ldg((const float4*)(_qp + 0));                            \
    qb##S[1].f = __ldg((const float4*)(_qp + 4));                            \
    qb##S[2].f = __ldg((const float4*)(_qp + 8));                            \
    qb##S[3].f = __ldg((const float4*)(_qp + 12));                           \
    vb##S = __ldg((const float2*)(vbase + (size_t)_t * (HV * DV)));          \
    gb##S = __ldg((const float4*)(gbase + (size_t)_t * (HV * 4)));           \
} while (0)

#define BODY(S, T) do {                                                     \
    const float eg = gb##S.x, beta = gb##S.y, qk = gb##S.z;                  \
    const ull egp = pack2(eg, eg);                                           \
    ull pr0 = 0, pr1 = 0, qs0 = 0, qs1 = 0;                                  \
    _Pragma("unroll")                                                        \
    for (int i = 0; i < 4; i++) {                                            \
        MUL2(st0[2*i],   st0[2*i],   egp);                                   \
        MUL2(st0[2*i+1], st0[2*i+1], egp);                                   \
        MUL2(st1[2*i],   st1[2*i],   egp);                                   \
        MUL2(st1[2*i+1], st1[2*i+1], egp);                                   \
        FMA2(pr0, kb##S[i].u[0], st0[2*i],   pr0);                           \
        FMA2(pr0, kb##S[i].u[1], st0[2*i+1], pr0);                           \
        FMA2(qs0, qb##S[i].u[0], st0[2*i],   qs0);                           \
        FMA2(qs0, qb##S[i].u[1], st0[2*i+1], qs0);                           \
        FMA2(pr1, kb##S[i].u[0], st1[2*i],   pr1);                           \
        FMA2(pr1, kb##S[i].u[1], st1[2*i+1], pr1);                           \
        FMA2(qs1, qb##S[i].u[0], st1[2*i],   qs1);                           \
        FMA2(qs1, qb##S[i].u[1], st1[2*i+1], qs1);                           \
    }                                                                        \
    float2 _pa = unpack2(pr0), _pb = unpack2(pr1);                           \
    float2 _qa = unpack2(qs0), _qb = unpack2(qs1);                           \
    float pred0 = _pa.x + _pa.y, pred1 = _pb.x + _pb.y;                      \
    float qsum0 = _qa.x + _qa.y, qsum1 = _qb.x + _qb.y;                      \
    _Pragma("unroll")                                                        \
    for (int o = 1; o < 8; o <<= 1) {                                        \
        pred0 += __shfl_xor_sync(0xffffffffu, pred0, o);                     \
        pred1 += __shfl_xor_sync(0xffffffffu, pred1, o);                     \
        qsum0 += __shfl_xor_sync(0xffffffffu, qsum0, o);                     \
        qsum1 += __shfl_xor_sync(0xffffffffu, qsum1, o);                     \
    }                                                                        \
    const float u0 = beta * (vb##S.x - pred0);                               \
    const float u1 = beta * (vb##S.y - pred1);                               \
    const ull up0 = pack2(u0, u0), up1 = pack2(u1, u1);                      \
    _Pragma("unroll")                                                        \
    for (int i = 0; i < 4; i++) {                                            \
        FMA2(st0[2*i],   kb##S[i].u[0], up0, st0[2*i]);                      \
        FMA2(st0[2*i+1], kb##S[i].u[1], up0, st0[2*i+1]);                    \
        FMA2(st1[2*i],   kb##S[i].u[0], up1, st1[2*i]);                      \
        FMA2(st1[2*i+1], kb##S[i].u[1], up1, st1[2*i+1]);                    \
    }                                                                        \
    if (p == 0) {                                                            \
        float2 oo = make_float2(fmaf(qk, u0, qsum0), fmaf(qk, u1, qsum1));   \
        *reinterpret_cast<float2*>(obase + (size_t)(T) * (HV * DV)) = oo;    \
    }                                                                        \
} while (0)

__global__ __launch_bounds__(256, 1) void rec_kernel(float* __restrict__ out)
{
    const int blk = blockIdx.x;
    const int b   = blk >> 6;
    const int h   = (blk >> 1) & 31;
    const int vh  = blk & 1;
    const int hk  = h >> 1;

    const int tid = threadIdx.x;
    const int c2  = tid >> 3;          // col-pair 0..31
    const int p   = tid & 7;           // k-slice 0..7 (16 dims)

    const float* kbase = g_kn + ((size_t)(b * S_LEN) * HK + hk) * DK + p * 16;
    const float* qbase = g_qn + ((size_t)(b * S_LEN) * HK + hk) * DK + p * 16;
    const float* vbase = g_v  + ((size_t)(b * S_LEN) * HV + h) * DV + vh * 64 + c2 * 2;
    const float* gbase = g_gate + ((size_t)(b * S_LEN) * HV + h) * 4;
    float*       obase = out  + ((size_t)(b * S_LEN) * HV + h) * DV + vh * 64 + c2 * 2;

    ull st0[8], st1[8];
#pragma unroll
    for (int i = 0; i < 8; i++) { st0[i] = 0ull; st1[i] = 0ull; }

    F4U kb0[4], kb1[4], qb0[4], qb1[4];
    float2 vb0, vb1;
    float4 gb0, gb1;

    FETCH(0, 0);
    FETCH(1, 1);

#pragma unroll 1
    for (int t = 0; t < S_LEN; t += 2) {
        BODY(0, t);
        { int tn = t + 2; if (tn >= S_LEN) tn = S_LEN - 1; FETCH(0, tn); }
        BODY(1, t + 1);
        { int tn = t + 3; if (tn >= S_LEN) tn = S_LEN - 1; FETCH(1, tn); }
    }
}

// ---------------- launch ----------------
extern "C" void kernel_launch(void* const* d_in, const int* in_sizes, int n_in,
                              void* d_out, int out_size)
{
    const float* mixed_qkv = (const float*)d_in[0];
    const float* bvec      = (const float*)d_in[1];
    const float* avec      = (const float*)d_in[2];
    const float* convw     = (const float*)d_in[3];
    const float* dt_bias   = (const float*)d_in[4];
    const float* alog      = (const float*)d_in[5];
    float* out = (float*)d_out;

    prep_kernel<<<NROWS, 256>>>(mixed_qkv, bvec, avec, convw, dt_bias, alog);
    rec_kernel<<<BQ * HV * 2, 256>>>(out);
}

// round 4
// speedup vs baseline: 1.6919x; 1.6919x over previous
#include <cuda_runtime.h>
#include <cuda_bf16.h>
#include <math.h>

#define BQ 2
#define S_LEN 2048
#define HK 16
#define HV 32
#define DK 128
#define DV 128
#define QKV 8192
#define NROWS (BQ * S_LEN)
#define TB 16   // tokens per smem batch in recurrence

typedef unsigned long long ull;

// ---------------- scratch (device globals; no runtime allocation) ----------------
__device__ float g_qn[(size_t)NROWS * HK * DK];    // l2norm(q) * scale
__device__ float g_kn[(size_t)NROWS * HK * DK];    // l2norm(k)
__device__ float g_v [(size_t)NROWS * HV * DV];
__device__ float g_gate[(size_t)NROWS * HV * 4];   // float4 per (row,h): eg, beta, -, -

// ---------------- packed f32x2 helpers ----------------
__device__ __forceinline__ ull pack2(float lo, float hi) {
    ull r;
    asm("mov.b64 %0, {%1,%2};" : "=l"(r) : "f"(lo), "f"(hi));
    return r;
}
__device__ __forceinline__ float2 unpack2(ull v) {
    float2 r;
    asm("mov.b64 {%0,%1}, %2;" : "=f"(r.x), "=f"(r.y) : "l"(v));
    return r;
}
#define FMA2(d, a, b, c) asm("fma.rn.f32x2 %0, %1, %2, %3;" : "=l"(d) : "l"(a), "l"(b), "l"(c))
#define MUL2(d, a, b)    asm("mul.rn.f32x2 %0, %1, %2;"     : "=l"(d) : "l"(a), "l"(b))
#define ADD2(d, a, b)    asm("add.rn.f32x2 %0, %1, %2;"     : "=l"(d) : "l"(a), "l"(b))

union F4U { float4 f; ull u[2]; };

// ---------------- kernel 1: conv + silu + l2norm + gating ----------------
__global__ __launch_bounds__(256) void prep_kernel(
    const float* __restrict__ x,      // [NROWS, QKV]
    const float* __restrict__ bvec,   // [NROWS, HV]
    const float* __restrict__ avec,   // [NROWS, HV]
    const float* __restrict__ w,      // [QKV, 4]
    const float* __restrict__ dt_bias,// [HV]
    const float* __restrict__ alog)   // [HV]
{
    const int row = blockIdx.x;
    const int s   = row & (S_LEN - 1);
    const int tid = threadIdx.x;

    __shared__ float ysm[QKV];            // 32 KB

    const float4* w4 = (const float4*)w;  // taps contiguous per channel

    // --- causal depthwise conv (width 4) + SiLU ---
    for (int base = tid * 4; base < QKV; base += 256 * 4) {
        float4 wv0 = __ldg(w4 + base + 0);
        float4 wv1 = __ldg(w4 + base + 1);
        float4 wv2 = __ldg(w4 + base + 2);
        float4 wv3 = __ldg(w4 + base + 3);
        const float* t0 = (const float*)&wv0;
        const float* t1 = (const float*)&wv1;
        const float* t2 = (const float*)&wv2;
        const float* t3 = (const float*)&wv3;
        float4 acc = make_float4(0.f, 0.f, 0.f, 0.f);
#pragma unroll
        for (int j = 0; j < 4; j++) {
            if (s - 3 + j >= 0) {
                const float4 xv = *reinterpret_cast<const float4*>(
                    x + (size_t)(row - 3 + j) * QKV + base);
                acc.x = fmaf(xv.x, t0[j], acc.x);
                acc.y = fmaf(xv.y, t1[j], acc.y);
                acc.z = fmaf(xv.z, t2[j], acc.z);
                acc.w = fmaf(xv.w, t3[j], acc.w);
            }
        }
        acc.x = acc.x / (1.f + __expf(-acc.x));
        acc.y = acc.y / (1.f + __expf(-acc.y));
        acc.z = acc.z / (1.f + __expf(-acc.z));
        acc.w = acc.w / (1.f + __expf(-acc.w));
        *reinterpret_cast<float4*>(ysm + base) = acc;
    }
    __syncthreads();

    const int wi   = tid >> 5;
    const int lane = tid & 31;
    const float qscale = 0.08838834764831845f; // 128^-0.5

    // --- l2 norms for 32 groups (16 q heads + 16 k heads) ---
    for (int gr = wi; gr < 32; gr += 8) {
        const float4 v4 = reinterpret_cast<const float4*>(ysm + gr * 128)[lane];
        float ss = v4.x * v4.x + v4.y * v4.y + v4.z * v4.z + v4.w * v4.w;
#pragma unroll
        for (int o = 16; o > 0; o >>= 1) ss += __shfl_xor_sync(0xffffffffu, ss, o);
        const bool isq = gr < 16;
        const float mul = rsqrtf(ss + 1e-6f) * (isq ? qscale : 1.f);
        float4 ov = make_float4(v4.x * mul, v4.y * mul, v4.z * mul, v4.w * mul);
        if (isq)
            reinterpret_cast<float4*>(g_qn + ((size_t)row * HK + gr) * DK)[lane] = ov;
        else
            reinterpret_cast<float4*>(g_kn + ((size_t)row * HK + (gr - 16)) * DK)[lane] = ov;
    }

    // --- v copy ---
    for (int i = tid * 4; i < HV * DV; i += 256 * 4)
        *reinterpret_cast<float4*>(g_v + (size_t)row * (HV * DV) + i) =
            *reinterpret_cast<const float4*>(ysm + 2 * HK * DK + i);

    // --- gating table (eg, beta) ---
    if (tid < HV) {
        const int h = tid;
        float aa = avec[(size_t)row * HV + h] + dt_bias[h];
        float sp = (aa > 20.f) ? aa : log1pf(expf(aa));
        float g  = -expf(alog[h]) * sp;
        float eg = expf(g);
        float bb = bvec[(size_t)row * HV + h];
        float beta = 1.f / (1.f + expf(-bb));
        float4 gv = make_float4(eg, beta, 0.f, 0.f);
        *reinterpret_cast<float4*>(g_gate + ((size_t)row * HV + h) * 4) = gv;
    }
}

// ---------------- kernel 2: gated delta-rule recurrence ----------------
// grid 128 = (b, h, vh). 256 threads = 64 chains x 4 k-slices of 32 dims.
// Thread (c, p): state S[32p..32p+32, col] as 16 packed f32x2.
// Order per token: decay+pred -> shfl(2) -> u -> update (next token may proceed)
//                  -> qsum on post-update state -> shfl(2) -> store (off critical path).
// smem slices padded [4][36] so the 4 p-lanes' LDS.128 hit disjoint 16B bank
// segments (8x c-broadcast): conflict-free single-phase.
__global__ __launch_bounds__(256, 1) void rec_kernel(float* __restrict__ out)
{
    const int blk = blockIdx.x;
    const int b   = blk >> 6;
    const int h   = (blk >> 1) & 31;
    const int vh  = blk & 1;
    const int hk  = h >> 1;

    const int tid = threadIdx.x;
    const int c   = tid >> 2;          // chain 0..63
    const int p   = tid & 3;           // k-slice 0..3 (32 dims)

    __shared__ float sk[2][TB][4][36];
    __shared__ float sq[2][TB][4][36];
    __shared__ float sv[2][TB][64];
    __shared__ float4 sg[2][TB];

    ull st[16];
#pragma unroll
    for (int i = 0; i < 16; i++) st[i] = 0ull;

    const float* kbase = g_kn + ((size_t)(b * S_LEN) * HK + hk) * DK;
    const float* qbase = g_qn + ((size_t)(b * S_LEN) * HK + hk) * DK;
    const float* vbase = g_v  + ((size_t)(b * S_LEN) * HV + h) * DV + vh * 64;
    const float* gbase = g_gate + ((size_t)(b * S_LEN) * HV + h) * 4;
    const size_t qk_stride = (size_t)HK * DK;
    const size_t v_stride  = (size_t)HV * DV;

    auto load_batch = [&](int buf, int t0) {
        // k and q: TB tokens x 32 float4-chunks each (512 chunks, 2 rounds)
#pragma unroll
        for (int rep = 0; rep < 2; rep++) {
            int i  = tid + rep * 256;
            int tt = i >> 5, j = i & 31;
            float4 kv = __ldg((const float4*)(kbase + (size_t)(t0 + tt) * qk_stride) + j);
            *reinterpret_cast<float4*>(&sk[buf][tt][j >> 3][(j & 7) * 4]) = kv;
            float4 qv = __ldg((const float4*)(qbase + (size_t)(t0 + tt) * qk_stride) + j);
            *reinterpret_cast<float4*>(&sq[buf][tt][j >> 3][(j & 7) * 4]) = qv;
        }
        // v: TB x 16 float4-chunks = 256
        {
            int tt = tid >> 4, j = tid & 15;
            *reinterpret_cast<float4*>(&sv[buf][tt][j * 4]) =
                __ldg((const float4*)(vbase + (size_t)(t0 + tt) * v_stride) + j);
        }
        if (tid < TB)
            sg[buf][tid] = __ldg((const float4*)(gbase + (size_t)(t0 + tid) * (HV * 4)));
    };

    load_batch(0, 0);
    __syncthreads();
    int buf = 0;

    float* obase = out + ((size_t)(b * S_LEN) * HV + h) * DV + vh * 64 + c;

#pragma unroll 1
    for (int t0 = 0; t0 < S_LEN; t0 += TB) {
        if (t0 + TB < S_LEN) load_batch(buf ^ 1, t0 + TB);

#pragma unroll 1
        for (int tt = 0; tt < TB; tt++) {
            const float4 g4 = sg[buf][tt];
            const float eg = g4.x, beta = g4.y;
            const ull egp = pack2(eg, eg);

            // k slice: 32 floats = 8 float4
            F4U kr[8];
            const float* kp = &sk[buf][tt][p][0];
#pragma unroll
            for (int i = 0; i < 8; i++)
                kr[i].f = *reinterpret_cast<const float4*>(kp + i * 4);

            // decay + pred = k . (eg*S), 4 accumulators
            ull pr0 = 0, pr1 = 0, pr2 = 0, pr3 = 0;
#pragma unroll
            for (int i = 0; i < 4; i++) {
                MUL2(st[4*i+0], st[4*i+0], egp);
                MUL2(st[4*i+1], st[4*i+1], egp);
                MUL2(st[4*i+2], st[4*i+2], egp);
                MUL2(st[4*i+3], st[4*i+3], egp);
                FMA2(pr0, kr[2*i].u[0],   st[4*i+0], pr0);
                FMA2(pr1, kr[2*i].u[1],   st[4*i+1], pr1);
                FMA2(pr2, kr[2*i+1].u[0], st[4*i+2], pr2);
                FMA2(pr3, kr[2*i+1].u[1], st[4*i+3], pr3);
            }
            ull prA, prB, prC;
            ADD2(prA, pr0, pr1);
            ADD2(prB, pr2, pr3);
            ADD2(prC, prA, prB);
            float2 pf = unpack2(prC);
            float pred = pf.x + pf.y;
            pred += __shfl_xor_sync(0xffffffffu, pred, 1);
            pred += __shfl_xor_sync(0xffffffffu, pred, 2);

            const float u = beta * (sv[buf][tt][c] - pred);
            const ull up = pack2(u, u);

            // state update: S += k*u  (next token's chain unblocked after this)
#pragma unroll
            for (int i = 0; i < 8; i++) {
                FMA2(st[2*i],   kr[i].u[0], up, st[2*i]);
                FMA2(st[2*i+1], kr[i].u[1], up, st[2*i+1]);
            }

            // output: o = q . S_post  (off the recurrence critical path)
            F4U qr[8];
            const float* qp = &sq[buf][tt][p][0];
#pragma unroll
            for (int i = 0; i < 8; i++)
                qr[i].f = *reinterpret_cast<const float4*>(qp + i * 4);

            ull qs0 = 0, qs1 = 0, qs2 = 0, qs3 = 0;
#pragma unroll
            for (int i = 0; i < 4; i++) {
                FMA2(qs0, qr[2*i].u[0],   st[4*i+0], qs0);
                FMA2(qs1, qr[2*i].u[1],   st[4*i+1], qs1);
                FMA2(qs2, qr[2*i+1].u[0], st[4*i+2], qs2);
                FMA2(qs3, qr[2*i+1].u[1], st[4*i+3], qs3);
            }
            ull qsA, qsB, qsC;
            ADD2(qsA, qs0, qs1);
            ADD2(qsB, qs2, qs3);
            ADD2(qsC, qsA, qsB);
            float2 qf = unpack2(qsC);
            float oo = qf.x + qf.y;
            oo += __shfl_xor_sync(0xffffffffu, oo, 1);
            oo += __shfl_xor_sync(0xffffffffu, oo, 2);

            if (p == 0) obase[(size_t)(t0 + tt) * (HV * DV)] = oo;
        }
        __syncthreads();
        buf ^= 1;
    }
}

// ---------------- launch ----------------
extern "C" void kernel_launch(void* const* d_in, const int* in_sizes, int n_in,
                              void* d_out, int out_size)
{
    const float* mixed_qkv = (const float*)d_in[0];
    const float* bvec      = (const float*)d_in[1];
    const float* avec      = (const float*)d_in[2];
    const float* convw     = (const float*)d_in[3];
    const float* dt_bias   = (const float*)d_in[4];
    const float* alog      = (const float*)d_in[5];
    float* out = (float*)d_out;

    prep_kernel<<<NROWS, 256>>>(mixed_qkv, bvec, avec, convw, dt_bias, alog);
    rec_kernel<<<BQ * HV * 2, 256>>>(out);
}